// round 2
// baseline (speedup 1.0000x reference)
#include <cuda_runtime.h>
#include <math.h>
#include <stdint.h>

#define NV 6890
#define NF 13776
#define NB 2

// winding: split triangle dim SW ways
#define SW 8
#define WCHUNK 1722            // NF/SW
#define WTILE 64

// pairwise: split i dim SP ways, 2 j's per thread
#define SP 24
#define PCHUNK 288             // ceil(NV/SP) -> 24*288 = 6912 >= 6890
#define TI 128

__device__ float4 d_triA[NB * NF];
__device__ float4 d_triB[NB * NF];
__device__ float4 d_triC[NB * NF];
__device__ float  d_wnp[SW][NB * NV];
__device__ float  d_pmin[SP][NB * NV];

__device__ __forceinline__ float rcp_fast(float x) {
    float r; asm("rcp.approx.f32 %0, %1;" : "=f"(r) : "f"(x)); return r;
}
__device__ __forceinline__ float rsqrt_fast(float x) {
    float r; asm("rsqrt.approx.f32 %0, %1;" : "=f"(r) : "f"(x)); return r;
}

// atan2 with ~5e-7 rad abs error; matches numpy conventions at
// (0, +x), (0, -x), (+-0, +-0) for the cases reachable here.
__device__ __forceinline__ float fast_atan2f(float y, float x) {
    float ax = fabsf(x), ay = fabsf(y);
    float mx = fmaxf(ax, ay), mn = fminf(ax, ay);
    float t = mn * rcp_fast(mx);
    t = (mx == 0.0f) ? 0.0f : t;          // atan2(0,0) path -> 0
    float s = t * t;
    float u;
    u = 0.00282363896258175373077393f;
    u = fmaf(u, s, -0.0159569028764963150024414f);
    u = fmaf(u, s,  0.0425049886107444763183594f);
    u = fmaf(u, s, -0.0748900920152664184570312f);
    u = fmaf(u, s,  0.106347933411598205566406f);
    u = fmaf(u, s, -0.142027363181114196777344f);
    u = fmaf(u, s,  0.199926957488059997558594f);
    u = fmaf(u, s, -0.333331018686294555664062f);
    float r = fmaf(u * s, t, t);          // atan(mn/mx) in [0, pi/4]
    if (ay > ax) r = 1.57079632679489662f - r;
    if (x < 0.0f) r = 3.14159265358979323f - r;
    return copysignf(r, y);
}

__global__ void gather_tris(const float* __restrict__ verts,
                            const int* __restrict__ faces) {
    int idx = blockIdx.x * blockDim.x + threadIdx.x;
    if (idx >= NB * NF) return;
    int b = idx / NF, t = idx - b * NF;
    int i0 = faces[3 * t + 0];
    int i1 = faces[3 * t + 1];
    int i2 = faces[3 * t + 2];
    const float* vb = verts + (size_t)b * NV * 3;
    d_triA[idx] = make_float4(vb[3 * i0], vb[3 * i0 + 1], vb[3 * i0 + 2], 0.f);
    d_triB[idx] = make_float4(vb[3 * i1], vb[3 * i1 + 1], vb[3 * i1 + 2], 0.f);
    d_triC[idx] = make_float4(vb[3 * i2], vb[3 * i2 + 1], vb[3 * i2 + 2], 0.f);
}

__global__ void winding_kernel(const float* __restrict__ verts) {
    __shared__ float4 sA[WTILE], sB[WTILE], sC[WTILE];
    const int b = blockIdx.z;
    const int s = blockIdx.y;
    const int p = blockIdx.x * blockDim.x + threadIdx.x;
    const bool valid = p < NV;

    float px = 0.f, py = 0.f, pz = 0.f;
    if (valid) {
        const float* vp = verts + ((size_t)b * NV + p) * 3;
        px = vp[0]; py = vp[1]; pz = vp[2];
    }

    const int t0 = s * WCHUNK;
    const int t1 = min(NF, t0 + WCHUNK);
    float acc = 0.f;

    for (int base = t0; base < t1; base += WTILE) {
        int cnt = min(WTILE, t1 - base);
        __syncthreads();
        for (int k = threadIdx.x; k < cnt; k += blockDim.x) {
            sA[k] = d_triA[b * NF + base + k];
            sB[k] = d_triB[b * NF + base + k];
            sC[k] = d_triC[b * NF + base + k];
        }
        __syncthreads();
        if (valid) {
            #pragma unroll 2
            for (int k = 0; k < cnt; k++) {
                float4 A = sA[k], B = sB[k], C = sC[k];
                float ax = A.x - px, ay = A.y - py, az = A.z - pz;
                float bx = B.x - px, by = B.y - py, bz = B.z - pz;
                float cx = C.x - px, cy = C.y - py, cz = C.z - pz;

                float na2 = fmaf(ax, ax, fmaf(ay, ay, az * az));
                float nb2 = fmaf(bx, bx, fmaf(by, by, bz * bz));
                float nc2 = fmaf(cx, cx, fmaf(cy, cy, cz * cz));
                float na = (na2 > 0.f) ? na2 * rsqrt_fast(na2) : 0.f;
                float nb = (nb2 > 0.f) ? nb2 * rsqrt_fast(nb2) : 0.f;
                float nc = (nc2 > 0.f) ? nc2 * rsqrt_fast(nc2) : 0.f;

                float ux = fmaf(by, cz, -(bz * cy));
                float uy = fmaf(bz, cx, -(bx * cz));
                float uz = fmaf(bx, cy, -(by * cx));

                float det = fmaf(az, uz, fmaf(ay, uy, ax * ux));
                float ab  = fmaf(az, bz, fmaf(ay, by, ax * bx));
                float bc  = fmaf(bz, cz, fmaf(by, cy, bx * cx));
                float ca  = fmaf(cz, az, fmaf(cy, ay, cx * ax));

                float denom = fmaf(ca, nb, fmaf(bc, na, fmaf(ab, nc, na * nb * nc)));
                acc += fast_atan2f(det, denom);
            }
        }
    }
    if (valid) d_wnp[s][b * NV + p] = acc;
}

__global__ void pairwise_kernel(const float* __restrict__ verts,
                                const int* __restrict__ gm) {
    __shared__ float sx0[TI], sy0[TI], sz0[TI], sq0[TI];
    __shared__ float sx1[TI], sy1[TI], sz1[TI], sq1[TI];

    const int s  = blockIdx.y;
    const int j0 = (blockIdx.x * blockDim.x + threadIdx.x) * 2;
    const bool jv = j0 < NV;   // NV even -> j0+1 < NV too

    float xa0=0,ya0=0,za0=0,qa0=0, xa1=0,ya1=0,za1=0,qa1=0;   // batch 0, j0 / j0+1
    float xb0=0,yb0=0,zb0=0,qb0=0, xb1=0,yb1=0,zb1=0,qb1=0;   // batch 1
    if (jv) {
        const float* v = verts + (size_t)j0 * 3;
        xa0 = v[0]; ya0 = v[1]; za0 = v[2];
        xa1 = v[3]; ya1 = v[4]; za1 = v[5];
        qa0 = (xa0*xa0 + ya0*ya0) + za0*za0;
        qa1 = (xa1*xa1 + ya1*ya1) + za1*za1;
        const float* w = verts + ((size_t)NV + j0) * 3;
        xb0 = w[0]; yb0 = w[1]; zb0 = w[2];
        xb1 = w[3]; yb1 = w[4]; zb1 = w[5];
        qb0 = (xb0*xb0 + yb0*yb0) + zb0*zb0;
        qb1 = (xb1*xb1 + yb1*yb1) + zb1*zb1;
    }

    const float INF = __int_as_float(0x7f800000);
    float m00 = INF, m01 = INF, m10 = INF, m11 = INF;

    const int i0 = s * PCHUNK;
    const int i1 = min(NV, i0 + PCHUNK);

    for (int base = i0; base < i1; base += TI) {
        int cnt = min(TI, i1 - base);
        __syncthreads();
        for (int k = threadIdx.x; k < cnt; k += blockDim.x) {
            int i = base + k;
            const float* v = verts + (size_t)i * 3;
            float x = v[0], y = v[1], z = v[2];
            sx0[k] = x; sy0[k] = y; sz0[k] = z;
            sq0[k] = (x*x + y*y) + z*z;
            const float* w = verts + ((size_t)NV + i) * 3;
            x = w[0]; y = w[1]; z = w[2];
            sx1[k] = x; sy1[k] = y; sz1[k] = z;
            sq1[k] = (x*x + y*y) + z*z;
        }
        __syncthreads();
        if (jv) {
            const int* mp = gm + (size_t)base * NV + j0;
            for (int k = 0; k < cnt; k++) {
                int2 mm = *(const int2*)mp;
                mp += NV;
                // batch 0
                float xi = sx0[k], yi = sy0[k], zi = sz0[k], qi = sq0[k];
                float dot0 = fmaf(zi, za0, fmaf(yi, ya0, xi * xa0));
                float d2_0 = fmaf(-2.f, dot0, qi + qa0);
                float dot1 = fmaf(zi, za1, fmaf(yi, ya1, xi * xa1));
                float d2_1 = fmaf(-2.f, dot1, qi + qa1);
                if (mm.x) m00 = fminf(m00, d2_0);
                if (mm.y) m01 = fminf(m01, d2_1);
                // batch 1
                xi = sx1[k]; yi = sy1[k]; zi = sz1[k]; qi = sq1[k];
                float e0 = fmaf(zi, zb0, fmaf(yi, yb0, xi * xb0));
                float f0 = fmaf(-2.f, e0, qi + qb0);
                float e1 = fmaf(zi, zb1, fmaf(yi, yb1, xi * xb1));
                float f1 = fmaf(-2.f, e1, qi + qb1);
                if (mm.x) m10 = fminf(m10, f0);
                if (mm.y) m11 = fminf(m11, f1);
            }
        }
    }
    if (jv) {
        d_pmin[s][j0]          = m00;
        d_pmin[s][j0 + 1]      = m01;
        d_pmin[s][NV + j0]     = m10;
        d_pmin[s][NV + j0 + 1] = m11;
    }
}

__global__ void finalize_kernel(float* __restrict__ out) {
    int idx = blockIdx.x * blockDim.x + threadIdx.x;
    if (idx >= NB * NV) return;
    const float INF = __int_as_float(0x7f800000);
    float mn = INF;
    #pragma unroll
    for (int s = 0; s < SP; s++) mn = fminf(mn, d_pmin[s][idx]);
    float v = sqrtf(fmaxf(mn, 1e-12f));

    float acc = 0.f;
    #pragma unroll
    for (int s = 0; s < SW; s++) acc += d_wnp[s][idx];
    float wn = (2.0f * acc) / 12.566370614359172f;   // 4*pi as f32

    out[idx]               = v;
    out[NB * NV + idx]     = (v < 0.02f) ? 1.0f : 0.0f;
    out[2 * NB * NV + idx] = (wn <= 0.99f) ? 1.0f : 0.0f;
}

extern "C" void kernel_launch(void* const* d_in, const int* in_sizes, int n_in,
                              void* d_out, int out_size) {
    const float* verts = (const float*)d_in[0];
    const int*   faces = (const int*)d_in[1];
    const int*   gm    = (const int*)d_in[2];
    float* out = (float*)d_out;

    gather_tris<<<(NB * NF + 255) / 256, 256>>>(verts, faces);

    dim3 gw((NV + 127) / 128, SW, NB);   // 54 x 8 x 2 = 864 blocks
    winding_kernel<<<gw, 128>>>(verts);

    dim3 gp((NV + 511) / 512, SP);       // 14 x 24 = 336 blocks
    pairwise_kernel<<<gp, 256>>>(verts, gm);

    finalize_kernel<<<(NB * NV + 255) / 256, 256>>>(out);
}

// round 4
// speedup vs baseline: 1.1117x; 1.1117x over previous
#include <cuda_runtime.h>
#include <math.h>
#include <stdint.h>

#define NV 6890
#define NF 13776
#define NB 2

// winding: split triangle dim SW ways; 2 points per thread
#define SW 16
#define WCHUNK 861             // NF/SW exact (16*861 = 13776)
#define WTILE 128
#define PHALF 3456             // 54 blocks * 64 threads

// pairwise: split i dim SP ways, 2 j's per thread
#define SP 24
#define PCHUNK 288
#define TI 128

__device__ float4 d_triA[NB * NF];
__device__ float4 d_triB[NB * NF];
__device__ float4 d_triC[NB * NF];
__device__ float  d_wnp[SW][NB * NV];
__device__ float  d_pmin[SP][NB * NV];

__device__ __forceinline__ float rcp_fast(float x) {
    float r; asm("rcp.approx.f32 %0, %1;" : "=f"(r) : "f"(x)); return r;
}
__device__ __forceinline__ float rsqrt_fast(float x) {
    float r; asm("rsqrt.approx.f32 %0, %1;" : "=f"(r) : "f"(x)); return r;
}

__device__ __forceinline__ float fast_atan2f(float y, float x) {
    float ax = fabsf(x), ay = fabsf(y);
    float mx = fmaxf(ax, ay), mn = fminf(ax, ay);
    float t = mn * rcp_fast(fmaxf(mx, 1e-37f));   // mx==0 -> t = 0
    float s = t * t;
    float u;
    u = 0.00282363896258175373077393f;
    u = fmaf(u, s, -0.0159569028764963150024414f);
    u = fmaf(u, s,  0.0425049886107444763183594f);
    u = fmaf(u, s, -0.0748900920152664184570312f);
    u = fmaf(u, s,  0.106347933411598205566406f);
    u = fmaf(u, s, -0.142027363181114196777344f);
    u = fmaf(u, s,  0.199926957488059997558594f);
    u = fmaf(u, s, -0.333331018686294555664062f);
    float r = fmaf(u * s, t, t);                  // atan(mn/mx) in [0, pi/4]
    r = (ay > ax) ? 1.57079632679489662f - r : r;
    r = (x < 0.0f) ? 3.14159265358979323f - r : r;
    return copysignf(r, y);
}

// one point-triangle solid-angle contribution
__device__ __forceinline__ float wn_contrib(
    float px, float py, float pz,
    const float4& A, const float4& B, const float4& C)
{
    float ax = A.x - px, ay = A.y - py, az = A.z - pz;
    float bx = B.x - px, by = B.y - py, bz = B.z - pz;
    float cx = C.x - px, cy = C.y - py, cz = C.z - pz;

    float na2 = fmaf(ax, ax, fmaf(ay, ay, az * az));
    float nb2 = fmaf(bx, bx, fmaf(by, by, bz * bz));
    float nc2 = fmaf(cx, cx, fmaf(cy, cy, cz * cz));
    float na = na2 * rsqrt_fast(fmaxf(na2, 1e-37f));
    float nb = nb2 * rsqrt_fast(fmaxf(nb2, 1e-37f));
    float nc = nc2 * rsqrt_fast(fmaxf(nc2, 1e-37f));

    float ux = fmaf(by, cz, -(bz * cy));
    float uy = fmaf(bz, cx, -(bx * cz));
    float uz = fmaf(bx, cy, -(by * cx));

    float det = fmaf(az, uz, fmaf(ay, uy, ax * ux));
    float ab  = fmaf(az, bz, fmaf(ay, by, ax * bx));
    float bc  = fmaf(bz, cz, fmaf(by, cy, bx * cx));
    float ca  = fmaf(cz, az, fmaf(cy, ay, cx * ax));

    float denom = fmaf(ca, nb, fmaf(bc, na, fmaf(ab, nc, na * nb * nc)));
    return fast_atan2f(det, denom);
}

__global__ void gather_tris(const float* __restrict__ verts,
                            const int* __restrict__ faces) {
    int idx = blockIdx.x * blockDim.x + threadIdx.x;
    if (idx >= NB * NF) return;
    int b = idx / NF, t = idx - b * NF;
    int i0 = faces[3 * t + 0];
    int i1 = faces[3 * t + 1];
    int i2 = faces[3 * t + 2];
    const float* vb = verts + (size_t)b * NV * 3;
    d_triA[idx] = make_float4(vb[3 * i0], vb[3 * i0 + 1], vb[3 * i0 + 2], 0.f);
    d_triB[idx] = make_float4(vb[3 * i1], vb[3 * i1 + 1], vb[3 * i1 + 2], 0.f);
    d_triC[idx] = make_float4(vb[3 * i2], vb[3 * i2 + 1], vb[3 * i2 + 2], 0.f);
}

__global__ void __launch_bounds__(64) winding_kernel(const float* __restrict__ verts) {
    __shared__ float4 sA[WTILE], sB[WTILE], sC[WTILE];
    const int b = blockIdx.z;
    const int s = blockIdx.y;
    const int p0 = blockIdx.x * 64 + threadIdx.x;        // < PHALF always
    const int p1r = p0 + PHALF;
    const int p1 = min(p1r, NV - 1);                     // compute clamped, maybe discard

    const float* vp0 = verts + ((size_t)b * NV + p0) * 3;
    float px0 = vp0[0], py0 = vp0[1], pz0 = vp0[2];
    const float* vp1 = verts + ((size_t)b * NV + p1) * 3;
    float px1 = vp1[0], py1 = vp1[1], pz1 = vp1[2];

    const int t0 = s * WCHUNK;
    const int t1 = t0 + WCHUNK;
    float acc0 = 0.f, acc1 = 0.f;

    for (int base = t0; base < t1; base += WTILE) {
        int cnt = min(WTILE, t1 - base);
        __syncthreads();
        for (int k = threadIdx.x; k < cnt; k += 64) {
            sA[k] = d_triA[b * NF + base + k];
            sB[k] = d_triB[b * NF + base + k];
            sC[k] = d_triC[b * NF + base + k];
        }
        __syncthreads();
        #pragma unroll 2
        for (int k = 0; k < cnt; k++) {
            float4 A = sA[k], B = sB[k], C = sC[k];
            acc0 += wn_contrib(px0, py0, pz0, A, B, C);
            acc1 += wn_contrib(px1, py1, pz1, A, B, C);
        }
    }
    d_wnp[s][b * NV + p0] = acc0;
    if (p1r < NV) d_wnp[s][b * NV + p1r] = acc1;
}

__global__ void pairwise_kernel(const float* __restrict__ verts,
                                const int* __restrict__ gm) {
    __shared__ float sx0[TI], sy0[TI], sz0[TI], sq0[TI];
    __shared__ float sx1[TI], sy1[TI], sz1[TI], sq1[TI];

    const int s  = blockIdx.y;
    const int j0 = (blockIdx.x * blockDim.x + threadIdx.x) * 2;
    const bool jv = j0 < NV;

    float xa0=0,ya0=0,za0=0,qa0=0, xa1=0,ya1=0,za1=0,qa1=0;
    float xb0=0,yb0=0,zb0=0,qb0=0, xb1=0,yb1=0,zb1=0,qb1=0;
    if (jv) {
        const float* v = verts + (size_t)j0 * 3;
        xa0 = v[0]; ya0 = v[1]; za0 = v[2];
        xa1 = v[3]; ya1 = v[4]; za1 = v[5];
        qa0 = (xa0*xa0 + ya0*ya0) + za0*za0;
        qa1 = (xa1*xa1 + ya1*ya1) + za1*za1;
        const float* w = verts + ((size_t)NV + j0) * 3;
        xb0 = w[0]; yb0 = w[1]; zb0 = w[2];
        xb1 = w[3]; yb1 = w[4]; zb1 = w[5];
        qb0 = (xb0*xb0 + yb0*yb0) + zb0*zb0;
        qb1 = (xb1*xb1 + yb1*yb1) + zb1*zb1;
    }

    const float INF = __int_as_float(0x7f800000);
    float m00 = INF, m01 = INF, m10 = INF, m11 = INF;

    const int i0 = s * PCHUNK;
    const int i1 = min(NV, i0 + PCHUNK);

    for (int base = i0; base < i1; base += TI) {
        int cnt = min(TI, i1 - base);
        __syncthreads();
        for (int k = threadIdx.x; k < cnt; k += blockDim.x) {
            int i = base + k;
            const float* v = verts + (size_t)i * 3;
            float x = v[0], y = v[1], z = v[2];
            sx0[k] = x; sy0[k] = y; sz0[k] = z;
            sq0[k] = (x*x + y*y) + z*z;
            const float* w = verts + ((size_t)NV + i) * 3;
            x = w[0]; y = w[1]; z = w[2];
            sx1[k] = x; sy1[k] = y; sz1[k] = z;
            sq1[k] = (x*x + y*y) + z*z;
        }
        __syncthreads();
        if (jv) {
            const int* mp = gm + (size_t)base * NV + j0;
            for (int k = 0; k < cnt; k++) {
                int2 mm = *(const int2*)mp;
                mp += NV;
                float xi = sx0[k], yi = sy0[k], zi = sz0[k], qi = sq0[k];
                float dot0 = fmaf(zi, za0, fmaf(yi, ya0, xi * xa0));
                float d2_0 = fmaf(-2.f, dot0, qi + qa0);
                float dot1 = fmaf(zi, za1, fmaf(yi, ya1, xi * xa1));
                float d2_1 = fmaf(-2.f, dot1, qi + qa1);
                if (mm.x) m00 = fminf(m00, d2_0);
                if (mm.y) m01 = fminf(m01, d2_1);
                xi = sx1[k]; yi = sy1[k]; zi = sz1[k]; qi = sq1[k];
                float e0 = fmaf(zi, zb0, fmaf(yi, yb0, xi * xb0));
                float f0 = fmaf(-2.f, e0, qi + qb0);
                float e1 = fmaf(zi, zb1, fmaf(yi, yb1, xi * xb1));
                float f1 = fmaf(-2.f, e1, qi + qb1);
                if (mm.x) m10 = fminf(m10, f0);
                if (mm.y) m11 = fminf(m11, f1);
            }
        }
    }
    if (jv) {
        d_pmin[s][j0]          = m00;
        d_pmin[s][j0 + 1]      = m01;
        d_pmin[s][NV + j0]     = m10;
        d_pmin[s][NV + j0 + 1] = m11;
    }
}

__global__ void finalize_kernel(float* __restrict__ out) {
    int idx = blockIdx.x * blockDim.x + threadIdx.x;
    if (idx >= NB * NV) return;
    const float INF = __int_as_float(0x7f800000);
    float mn = INF;
    #pragma unroll
    for (int s = 0; s < SP; s++) mn = fminf(mn, d_pmin[s][idx]);
    float v = sqrtf(fmaxf(mn, 1e-12f));

    float acc = 0.f;
    #pragma unroll
    for (int s = 0; s < SW; s++) acc += d_wnp[s][idx];
    float wn = (2.0f * acc) / 12.566370614359172f;

    out[idx]               = v;
    out[NB * NV + idx]     = (v < 0.02f) ? 1.0f : 0.0f;
    out[2 * NB * NV + idx] = (wn <= 0.99f) ? 1.0f : 0.0f;
}

extern "C" void kernel_launch(void* const* d_in, const int* in_sizes, int n_in,
                              void* d_out, int out_size) {
    const float* verts = (const float*)d_in[0];
    const int*   faces = (const int*)d_in[1];
    const int*   gm    = (const int*)d_in[2];
    float* out = (float*)d_out;

    gather_tris<<<(NB * NF + 255) / 256, 256>>>(verts, faces);

    dim3 gw(54, SW, NB);                 // 54 x 16 x 2 = 1728 blocks, 64 thr
    winding_kernel<<<gw, 64>>>(verts);

    dim3 gp((NV + 511) / 512, SP);       // 14 x 24 = 336 blocks
    pairwise_kernel<<<gp, 256>>>(verts, gm);

    finalize_kernel<<<(NB * NV + 255) / 256, 256>>>(out);
}

// round 5
// speedup vs baseline: 1.1399x; 1.0254x over previous
#include <cuda_runtime.h>
#include <math.h>
#include <stdint.h>

#define NV 6890
#define NF 13776
#define NB 2

// winding: split triangle dim SW ways; 2 points per thread packed in f32x2
#define SW 16
#define WCHUNK 861             // NF/SW exact
#define WTILE 128
#define PHALF 3456             // 54 blocks * 64 threads

// pairwise: split i dim SP ways, 2 j's per thread
#define SP 24
#define PCHUNK 288
#define TI 128

typedef unsigned long long u64;

__device__ float4 d_triA[NB * NF];
__device__ float4 d_triB[NB * NF];
__device__ float4 d_triC[NB * NF];
__device__ float  d_wnp[SW][NB * NV];
__device__ float  d_pmin[SP][NB * NV];

__device__ __forceinline__ float rcp_fast(float x) {
    float r; asm("rcp.approx.f32 %0, %1;" : "=f"(r) : "f"(x)); return r;
}
__device__ __forceinline__ float rsqrt_fast(float x) {
    float r; asm("rsqrt.approx.f32 %0, %1;" : "=f"(r) : "f"(x)); return r;
}

// ---- packed f32x2 helpers ----
__device__ __forceinline__ u64 pk(float lo, float hi) {
    u64 r; asm("mov.b64 %0, {%1, %2};" : "=l"(r) : "f"(lo), "f"(hi)); return r;
}
__device__ __forceinline__ void upk(u64 v, float& lo, float& hi) {
    asm("mov.b64 {%0, %1}, %2;" : "=f"(lo), "=f"(hi) : "l"(v));
}
__device__ __forceinline__ u64 f2add(u64 a, u64 b) {
    u64 d; asm("add.rn.f32x2 %0, %1, %2;" : "=l"(d) : "l"(a), "l"(b)); return d;
}
__device__ __forceinline__ u64 f2mul(u64 a, u64 b) {
    u64 d; asm("mul.rn.f32x2 %0, %1, %2;" : "=l"(d) : "l"(a), "l"(b)); return d;
}
__device__ __forceinline__ u64 f2fma(u64 a, u64 b, u64 c) {
    u64 d; asm("fma.rn.f32x2 %0, %1, %2, %3;" : "=l"(d) : "l"(a), "l"(b), "l"(c)); return d;
}
__device__ __forceinline__ u64 f2neg(u64 a) { return a ^ 0x8000000080000000ULL; }

__global__ void gather_tris(const float* __restrict__ verts,
                            const int* __restrict__ faces) {
    int idx = blockIdx.x * blockDim.x + threadIdx.x;
    if (idx >= NB * NF) return;
    int b = idx / NF, t = idx - b * NF;
    int i0 = faces[3 * t + 0];
    int i1 = faces[3 * t + 1];
    int i2 = faces[3 * t + 2];
    const float* vb = verts + (size_t)b * NV * 3;
    d_triA[idx] = make_float4(vb[3 * i0], vb[3 * i0 + 1], vb[3 * i0 + 2], 0.f);
    d_triB[idx] = make_float4(vb[3 * i1], vb[3 * i1 + 1], vb[3 * i1 + 2], 0.f);
    d_triC[idx] = make_float4(vb[3 * i2], vb[3 * i2 + 1], vb[3 * i2 + 2], 0.f);
}

__global__ void __launch_bounds__(64) winding_kernel(const float* __restrict__ verts) {
    // smem tile: 9 lane-duplicated coords per triangle (Ax Ay Az Bx By Bz Cx Cy Cz)
    __shared__ u64 sT[WTILE][9];
    const int b = blockIdx.z;
    const int s = blockIdx.y;
    const int p0 = blockIdx.x * 64 + threadIdx.x;   // < PHALF
    const int p1r = p0 + PHALF;
    const int p1 = min(p1r, NV - 1);

    const float* vp0 = verts + ((size_t)b * NV + p0) * 3;
    const float* vp1 = verts + ((size_t)b * NV + p1) * 3;
    // negated point coords, packed (lane0 = p0, lane1 = p1)
    const u64 npx = pk(-vp0[0], -vp1[0]);
    const u64 npy = pk(-vp0[1], -vp1[1]);
    const u64 npz = pk(-vp0[2], -vp1[2]);

    // atan2 poly constants, lane-duplicated (hoisted out of loop)
    const u64 K7 = pk( 0.00282363896258175373077393f,  0.00282363896258175373077393f);
    const u64 K6 = pk(-0.0159569028764963150024414f,  -0.0159569028764963150024414f);
    const u64 K5 = pk( 0.0425049886107444763183594f,   0.0425049886107444763183594f);
    const u64 K4 = pk(-0.0748900920152664184570312f,  -0.0748900920152664184570312f);
    const u64 K3 = pk( 0.106347933411598205566406f,    0.106347933411598205566406f);
    const u64 K2 = pk(-0.142027363181114196777344f,   -0.142027363181114196777344f);
    const u64 K1 = pk( 0.199926957488059997558594f,    0.199926957488059997558594f);
    const u64 K0 = pk(-0.333331018686294555664062f,   -0.333331018686294555664062f);

    const int t0 = s * WCHUNK;
    const int t1 = t0 + WCHUNK;
    u64 acc2 = 0ULL;   // packed (+0, +0)

    for (int base = t0; base < t1; base += WTILE) {
        int cnt = min(WTILE, t1 - base);
        __syncthreads();
        for (int k = threadIdx.x; k < cnt; k += 64) {
            float4 A = d_triA[b * NF + base + k];
            float4 B = d_triB[b * NF + base + k];
            float4 C = d_triC[b * NF + base + k];
            sT[k][0] = pk(A.x, A.x); sT[k][1] = pk(A.y, A.y); sT[k][2] = pk(A.z, A.z);
            sT[k][3] = pk(B.x, B.x); sT[k][4] = pk(B.y, B.y); sT[k][5] = pk(B.z, B.z);
            sT[k][6] = pk(C.x, C.x); sT[k][7] = pk(C.y, C.y); sT[k][8] = pk(C.z, C.z);
        }
        __syncthreads();
        #pragma unroll 2
        for (int k = 0; k < cnt; k++) {
            u64 ax = f2add(sT[k][0], npx);
            u64 ay = f2add(sT[k][1], npy);
            u64 az = f2add(sT[k][2], npz);
            u64 bx = f2add(sT[k][3], npx);
            u64 by = f2add(sT[k][4], npy);
            u64 bz = f2add(sT[k][5], npz);
            u64 cx = f2add(sT[k][6], npx);
            u64 cy = f2add(sT[k][7], npy);
            u64 cz = f2add(sT[k][8], npz);

            u64 na2 = f2fma(ax, ax, f2fma(ay, ay, f2mul(az, az)));
            u64 nb2 = f2fma(bx, bx, f2fma(by, by, f2mul(bz, bz)));
            u64 nc2 = f2fma(cx, cx, f2fma(cy, cy, f2mul(cz, cz)));

            float v0, v1;
            upk(na2, v0, v1);
            u64 ra = pk(rsqrt_fast(fmaxf(v0, 1e-37f)), rsqrt_fast(fmaxf(v1, 1e-37f)));
            upk(nb2, v0, v1);
            u64 rb = pk(rsqrt_fast(fmaxf(v0, 1e-37f)), rsqrt_fast(fmaxf(v1, 1e-37f)));
            upk(nc2, v0, v1);
            u64 rc = pk(rsqrt_fast(fmaxf(v0, 1e-37f)), rsqrt_fast(fmaxf(v1, 1e-37f)));
            u64 na = f2mul(na2, ra);
            u64 nb = f2mul(nb2, rb);
            u64 nc = f2mul(nc2, rc);

            u64 ux = f2fma(by, cz, f2neg(f2mul(bz, cy)));
            u64 uy = f2fma(bz, cx, f2neg(f2mul(bx, cz)));
            u64 uz = f2fma(bx, cy, f2neg(f2mul(by, cx)));

            u64 det = f2fma(az, uz, f2fma(ay, uy, f2mul(ax, ux)));
            u64 ab  = f2fma(az, bz, f2fma(ay, by, f2mul(ax, bx)));
            u64 bc  = f2fma(bz, cz, f2fma(by, cy, f2mul(bx, cx)));
            u64 ca  = f2fma(cz, az, f2fma(cy, ay, f2mul(cx, ax)));

            u64 den = f2fma(ca, nb, f2fma(bc, na, f2fma(ab, nc, f2mul(f2mul(na, nb), nc))));

            // packed atan2(det, den)
            float y0, y1, x0, x1;
            upk(det, y0, y1);
            upk(den, x0, x1);
            float ax0 = fabsf(x0), ay0 = fabsf(y0);
            float ax1 = fabsf(x1), ay1 = fabsf(y1);
            float mx0 = fmaxf(ax0, ay0), mn0 = fminf(ax0, ay0);
            float mx1 = fmaxf(ax1, ay1), mn1 = fminf(ax1, ay1);
            float tt0 = mn0 * rcp_fast(fmaxf(mx0, 1e-37f));
            float tt1 = mn1 * rcp_fast(fmaxf(mx1, 1e-37f));
            u64 t2 = pk(tt0, tt1);
            u64 s2 = f2mul(t2, t2);
            u64 u2 = K7;
            u2 = f2fma(u2, s2, K6);
            u2 = f2fma(u2, s2, K5);
            u2 = f2fma(u2, s2, K4);
            u2 = f2fma(u2, s2, K3);
            u2 = f2fma(u2, s2, K2);
            u2 = f2fma(u2, s2, K1);
            u2 = f2fma(u2, s2, K0);
            u64 r2 = f2fma(f2mul(u2, s2), t2, t2);
            float r0, r1;
            upk(r2, r0, r1);
            r0 = (ay0 > ax0) ? 1.57079632679489662f - r0 : r0;
            r1 = (ay1 > ax1) ? 1.57079632679489662f - r1 : r1;
            r0 = (x0 < 0.0f) ? 3.14159265358979323f - r0 : r0;
            r1 = (x1 < 0.0f) ? 3.14159265358979323f - r1 : r1;
            r0 = copysignf(r0, y0);
            r1 = copysignf(r1, y1);
            acc2 = f2add(acc2, pk(r0, r1));
        }
    }
    float a0, a1;
    upk(acc2, a0, a1);
    d_wnp[s][b * NV + p0] = a0;
    if (p1r < NV) d_wnp[s][b * NV + p1r] = a1;
}

__global__ void pairwise_kernel(const float* __restrict__ verts,
                                const int* __restrict__ gm) {
    __shared__ float sx0[TI], sy0[TI], sz0[TI], sq0[TI];
    __shared__ float sx1[TI], sy1[TI], sz1[TI], sq1[TI];

    const int s  = blockIdx.y;
    const int j0 = (blockIdx.x * blockDim.x + threadIdx.x) * 2;
    const bool jv = j0 < NV;

    float xa0=0,ya0=0,za0=0,qa0=0, xa1=0,ya1=0,za1=0,qa1=0;
    float xb0=0,yb0=0,zb0=0,qb0=0, xb1=0,yb1=0,zb1=0,qb1=0;
    if (jv) {
        const float* v = verts + (size_t)j0 * 3;
        xa0 = v[0]; ya0 = v[1]; za0 = v[2];
        xa1 = v[3]; ya1 = v[4]; za1 = v[5];
        qa0 = (xa0*xa0 + ya0*ya0) + za0*za0;
        qa1 = (xa1*xa1 + ya1*ya1) + za1*za1;
        const float* w = verts + ((size_t)NV + j0) * 3;
        xb0 = w[0]; yb0 = w[1]; zb0 = w[2];
        xb1 = w[3]; yb1 = w[4]; zb1 = w[5];
        qb0 = (xb0*xb0 + yb0*yb0) + zb0*zb0;
        qb1 = (xb1*xb1 + yb1*yb1) + zb1*zb1;
    }

    const float INF = __int_as_float(0x7f800000);
    float m00 = INF, m01 = INF, m10 = INF, m11 = INF;

    const int i0 = s * PCHUNK;
    const int i1 = min(NV, i0 + PCHUNK);

    for (int base = i0; base < i1; base += TI) {
        int cnt = min(TI, i1 - base);
        __syncthreads();
        for (int k = threadIdx.x; k < cnt; k += blockDim.x) {
            int i = base + k;
            const float* v = verts + (size_t)i * 3;
            float x = v[0], y = v[1], z = v[2];
            sx0[k] = x; sy0[k] = y; sz0[k] = z;
            sq0[k] = (x*x + y*y) + z*z;
            const float* w = verts + ((size_t)NV + i) * 3;
            x = w[0]; y = w[1]; z = w[2];
            sx1[k] = x; sy1[k] = y; sz1[k] = z;
            sq1[k] = (x*x + y*y) + z*z;
        }
        __syncthreads();
        if (jv) {
            const int* mp = gm + (size_t)base * NV + j0;
            for (int k = 0; k < cnt; k++) {
                int2 mm = *(const int2*)mp;
                mp += NV;
                float xi = sx0[k], yi = sy0[k], zi = sz0[k], qi = sq0[k];
                float dot0 = fmaf(zi, za0, fmaf(yi, ya0, xi * xa0));
                float d2_0 = fmaf(-2.f, dot0, qi + qa0);
                float dot1 = fmaf(zi, za1, fmaf(yi, ya1, xi * xa1));
                float d2_1 = fmaf(-2.f, dot1, qi + qa1);
                if (mm.x) m00 = fminf(m00, d2_0);
                if (mm.y) m01 = fminf(m01, d2_1);
                xi = sx1[k]; yi = sy1[k]; zi = sz1[k]; qi = sq1[k];
                float e0 = fmaf(zi, zb0, fmaf(yi, yb0, xi * xb0));
                float f0 = fmaf(-2.f, e0, qi + qb0);
                float e1 = fmaf(zi, zb1, fmaf(yi, yb1, xi * xb1));
                float f1 = fmaf(-2.f, e1, qi + qb1);
                if (mm.x) m10 = fminf(m10, f0);
                if (mm.y) m11 = fminf(m11, f1);
            }
        }
    }
    if (jv) {
        d_pmin[s][j0]          = m00;
        d_pmin[s][j0 + 1]      = m01;
        d_pmin[s][NV + j0]     = m10;
        d_pmin[s][NV + j0 + 1] = m11;
    }
}

__global__ void finalize_kernel(float* __restrict__ out) {
    int idx = blockIdx.x * blockDim.x + threadIdx.x;
    if (idx >= NB * NV) return;
    const float INF = __int_as_float(0x7f800000);
    float mn = INF;
    #pragma unroll
    for (int s = 0; s < SP; s++) mn = fminf(mn, d_pmin[s][idx]);
    float v = sqrtf(fmaxf(mn, 1e-12f));

    float acc = 0.f;
    #pragma unroll
    for (int s = 0; s < SW; s++) acc += d_wnp[s][idx];
    float wn = (2.0f * acc) / 12.566370614359172f;

    out[idx]               = v;
    out[NB * NV + idx]     = (v < 0.02f) ? 1.0f : 0.0f;
    out[2 * NB * NV + idx] = (wn <= 0.99f) ? 1.0f : 0.0f;
}

extern "C" void kernel_launch(void* const* d_in, const int* in_sizes, int n_in,
                              void* d_out, int out_size) {
    const float* verts = (const float*)d_in[0];
    const int*   faces = (const int*)d_in[1];
    const int*   gm    = (const int*)d_in[2];
    float* out = (float*)d_out;

    gather_tris<<<(NB * NF + 255) / 256, 256>>>(verts, faces);

    dim3 gw(54, SW, NB);                 // 1728 blocks, 64 thr
    winding_kernel<<<gw, 64>>>(verts);

    dim3 gp((NV + 511) / 512, SP);       // 336 blocks
    pairwise_kernel<<<gp, 256>>>(verts, gm);

    finalize_kernel<<<(NB * NV + 255) / 256, 256>>>(out);
}

// round 7
// speedup vs baseline: 1.2322x; 1.0810x over previous
#include <cuda_runtime.h>
#include <math.h>
#include <stdint.h>

#define NV 6890
#define NF 13776
#define NB 2

// winding: split triangle dim SW ways; 2 points per thread
#define SW 16
#define WCHUNK 861             // NF/SW exact
#define WTILE 128
#define PHALF 3456             // 54 blocks * 64 threads

// pairwise: split i dim SP ways, 2 j's per thread
#define SP 24
#define PCHUNK 288
#define TI 128

__device__ float4 d_triA[NB * NF];
__device__ float4 d_triB[NB * NF];
__device__ float4 d_triC[NB * NF];
__device__ float4 d_triN[NB * NF];     // (nx, ny, nz, d0)
__device__ float  d_wnp[SW][NB * NV];
__device__ float  d_pmin[SP][NB * NV];

__device__ __forceinline__ float rcp_fast(float x) {
    float r; asm("rcp.approx.f32 %0, %1;" : "=f"(r) : "f"(x)); return r;
}
__device__ __forceinline__ float sqrt_fast(float x) {
    float r; asm("sqrt.approx.f32 %0, %1;" : "=f"(r) : "f"(x)); return r;
}

__device__ __forceinline__ float fast_atan2f(float y, float x) {
    float ax = fabsf(x), ay = fabsf(y);
    float mx = fmaxf(ax, ay), mn = fminf(ax, ay);
    float t = mn * rcp_fast(fmaxf(mx, 1e-37f));   // mx==0 -> t = 0
    float s = t * t;
    float u;
    u = 0.00282363896258175373077393f;
    u = fmaf(u, s, -0.0159569028764963150024414f);
    u = fmaf(u, s,  0.0425049886107444763183594f);
    u = fmaf(u, s, -0.0748900920152664184570312f);
    u = fmaf(u, s,  0.106347933411598205566406f);
    u = fmaf(u, s, -0.142027363181114196777344f);
    u = fmaf(u, s,  0.199926957488059997558594f);
    u = fmaf(u, s, -0.333331018686294555664062f);
    float r = fmaf(u * s, t, t);                  // atan(mn/mx) in [0, pi/4]
    r = (ay > ax) ? 1.57079632679489662f - r : r;
    r = (x < 0.0f) ? 3.14159265358979323f - r : r;
    return copysignf(r, y);
}

// one point-triangle solid-angle contribution.
// npx/npy/npz are the NEGATED point coords (hoisted by caller).
__device__ __forceinline__ float wn_contrib(
    float npx, float npy, float npz,
    const float4& A, const float4& B, const float4& C, const float4& N)
{
    float ax = A.x + npx, ay = A.y + npy, az = A.z + npz;
    float bx = B.x + npx, by = B.y + npy, bz = B.z + npz;
    float cx = C.x + npx, cy = C.y + npy, cz = C.z + npz;

    float na2 = fmaf(ax, ax, fmaf(ay, ay, az * az));
    float nb2 = fmaf(bx, bx, fmaf(by, by, bz * bz));
    float nc2 = fmaf(cx, cx, fmaf(cy, cy, cz * cz));
    float na = sqrt_fast(na2);
    float nb = sqrt_fast(nb2);
    float nc = sqrt_fast(nc2);

    float ab  = fmaf(az, bz, fmaf(ay, by, ax * bx));
    float bc  = fmaf(bz, cz, fmaf(by, cy, bx * cx));
    float ca  = fmaf(cz, az, fmaf(cy, ay, cx * ax));

    // det[a;b;c] = d0 - p.n  =  fma chain on negated point
    float det = fmaf(npz, N.z, fmaf(npy, N.y, fmaf(npx, N.x, N.w)));

    float denom = fmaf(ca, nb, fmaf(bc, na, fmaf(ab, nc, (na * nb) * nc)));
    float r = fast_atan2f(det, denom);

    // p exactly a vertex of this triangle -> reference gives atan2(0,0)=0,
    // but expanded det is rounding garbage there. Exact-diff norms are
    // exactly zero iff p == vertex, so force 0. (ALU-pipe ops only.)
    float m = fminf(fminf(na2, nb2), nc2);
    return (m == 0.0f) ? 0.0f : r;
}

__global__ void gather_tris(const float* __restrict__ verts,
                            const int* __restrict__ faces) {
    int idx = blockIdx.x * blockDim.x + threadIdx.x;
    if (idx >= NB * NF) return;
    int b = idx / NF, t = idx - b * NF;
    int i0 = faces[3 * t + 0];
    int i1 = faces[3 * t + 1];
    int i2 = faces[3 * t + 2];
    const float* vb = verts + (size_t)b * NV * 3;
    float Axv = vb[3*i0], Ayv = vb[3*i0+1], Azv = vb[3*i0+2];
    float Bxv = vb[3*i1], Byv = vb[3*i1+1], Bzv = vb[3*i1+2];
    float Cxv = vb[3*i2], Cyv = vb[3*i2+1], Czv = vb[3*i2+2];
    d_triA[idx] = make_float4(Axv, Ayv, Azv, 0.f);
    d_triB[idx] = make_float4(Bxv, Byv, Bzv, 0.f);
    d_triC[idx] = make_float4(Cxv, Cyv, Czv, 0.f);

    // B x C
    float bcx = fmaf(Byv, Czv, -(Bzv * Cyv));
    float bcy = fmaf(Bzv, Cxv, -(Bxv * Czv));
    float bcz = fmaf(Bxv, Cyv, -(Byv * Cxv));
    // A x B
    float abx = fmaf(Ayv, Bzv, -(Azv * Byv));
    float aby = fmaf(Azv, Bxv, -(Axv * Bzv));
    float abz = fmaf(Axv, Byv, -(Ayv * Bxv));
    // C x A
    float cax = fmaf(Cyv, Azv, -(Czv * Ayv));
    float cay = fmaf(Czv, Axv, -(Cxv * Azv));
    float caz = fmaf(Cxv, Ayv, -(Cyv * Axv));

    float nx = abx + bcx + cax;
    float ny = aby + bcy + cay;
    float nz = abz + bcz + caz;
    float d0 = fmaf(Azv, bcz, fmaf(Ayv, bcy, Axv * bcx));   // A.(BxC)
    d_triN[idx] = make_float4(nx, ny, nz, d0);
}

__global__ void __launch_bounds__(64) winding_kernel(const float* __restrict__ verts) {
    __shared__ float4 sA[WTILE], sB[WTILE], sC[WTILE], sN[WTILE];
    const int b = blockIdx.z;
    const int s = blockIdx.y;
    const int p0 = blockIdx.x * 64 + threadIdx.x;   // < PHALF
    const int p1r = p0 + PHALF;
    const int p1 = min(p1r, NV - 1);

    const float* vp0 = verts + ((size_t)b * NV + p0) * 3;
    const float npx0 = -vp0[0], npy0 = -vp0[1], npz0 = -vp0[2];
    const float* vp1 = verts + ((size_t)b * NV + p1) * 3;
    const float npx1 = -vp1[0], npy1 = -vp1[1], npz1 = -vp1[2];

    const int t0 = s * WCHUNK;
    const int t1 = t0 + WCHUNK;
    float acc0 = 0.f, acc1 = 0.f;

    for (int base = t0; base < t1; base += WTILE) {
        int cnt = min(WTILE, t1 - base);
        __syncthreads();
        for (int k = threadIdx.x; k < cnt; k += 64) {
            sA[k] = d_triA[b * NF + base + k];
            sB[k] = d_triB[b * NF + base + k];
            sC[k] = d_triC[b * NF + base + k];
            sN[k] = d_triN[b * NF + base + k];
        }
        __syncthreads();
        #pragma unroll 2
        for (int k = 0; k < cnt; k++) {
            float4 A = sA[k], B = sB[k], C = sC[k], N = sN[k];
            acc0 += wn_contrib(npx0, npy0, npz0, A, B, C, N);
            acc1 += wn_contrib(npx1, npy1, npz1, A, B, C, N);
        }
    }
    d_wnp[s][b * NV + p0] = acc0;
    if (p1r < NV) d_wnp[s][b * NV + p1r] = acc1;
}

__global__ void pairwise_kernel(const float* __restrict__ verts,
                                const int* __restrict__ gm) {
    __shared__ float sx0[TI], sy0[TI], sz0[TI], sq0[TI];
    __shared__ float sx1[TI], sy1[TI], sz1[TI], sq1[TI];

    const int s  = blockIdx.y;
    const int j0 = (blockIdx.x * blockDim.x + threadIdx.x) * 2;
    const bool jv = j0 < NV;

    float xa0=0,ya0=0,za0=0,qa0=0, xa1=0,ya1=0,za1=0,qa1=0;
    float xb0=0,yb0=0,zb0=0,qb0=0, xb1=0,yb1=0,zb1=0,qb1=0;
    if (jv) {
        const float* v = verts + (size_t)j0 * 3;
        xa0 = v[0]; ya0 = v[1]; za0 = v[2];
        xa1 = v[3]; ya1 = v[4]; za1 = v[5];
        qa0 = (xa0*xa0 + ya0*ya0) + za0*za0;
        qa1 = (xa1*xa1 + ya1*ya1) + za1*za1;
        const float* w = verts + ((size_t)NV + j0) * 3;
        xb0 = w[0]; yb0 = w[1]; zb0 = w[2];
        xb1 = w[3]; yb1 = w[4]; zb1 = w[5];
        qb0 = (xb0*xb0 + yb0*yb0) + zb0*zb0;
        qb1 = (xb1*xb1 + yb1*yb1) + zb1*zb1;
    }

    const float INF = __int_as_float(0x7f800000);
    float m00 = INF, m01 = INF, m10 = INF, m11 = INF;

    const int i0 = s * PCHUNK;
    const int i1 = min(NV, i0 + PCHUNK);

    for (int base = i0; base < i1; base += TI) {
        int cnt = min(TI, i1 - base);
        __syncthreads();
        for (int k = threadIdx.x; k < cnt; k += blockDim.x) {
            int i = base + k;
            const float* v = verts + (size_t)i * 3;
            float x = v[0], y = v[1], z = v[2];
            sx0[k] = x; sy0[k] = y; sz0[k] = z;
            sq0[k] = (x*x + y*y) + z*z;
            const float* w = verts + ((size_t)NV + i) * 3;
            x = w[0]; y = w[1]; z = w[2];
            sx1[k] = x; sy1[k] = y; sz1[k] = z;
            sq1[k] = (x*x + y*y) + z*z;
        }
        __syncthreads();
        if (jv) {
            const int* mp = gm + (size_t)base * NV + j0;
            for (int k = 0; k < cnt; k++) {
                int2 mm = *(const int2*)mp;
                mp += NV;
                float xi = sx0[k], yi = sy0[k], zi = sz0[k], qi = sq0[k];
                float dot0 = fmaf(zi, za0, fmaf(yi, ya0, xi * xa0));
                float d2_0 = fmaf(-2.f, dot0, qi + qa0);
                float dot1 = fmaf(zi, za1, fmaf(yi, ya1, xi * xa1));
                float d2_1 = fmaf(-2.f, dot1, qi + qa1);
                if (mm.x) m00 = fminf(m00, d2_0);
                if (mm.y) m01 = fminf(m01, d2_1);
                xi = sx1[k]; yi = sy1[k]; zi = sz1[k]; qi = sq1[k];
                float e0 = fmaf(zi, zb0, fmaf(yi, yb0, xi * xb0));
                float f0 = fmaf(-2.f, e0, qi + qb0);
                float e1 = fmaf(zi, zb1, fmaf(yi, yb1, xi * xb1));
                float f1 = fmaf(-2.f, e1, qi + qb1);
                if (mm.x) m10 = fminf(m10, f0);
                if (mm.y) m11 = fminf(m11, f1);
            }
        }
    }
    if (jv) {
        d_pmin[s][j0]          = m00;
        d_pmin[s][j0 + 1]      = m01;
        d_pmin[s][NV + j0]     = m10;
        d_pmin[s][NV + j0 + 1] = m11;
    }
}

__global__ void finalize_kernel(float* __restrict__ out) {
    int idx = blockIdx.x * blockDim.x + threadIdx.x;
    if (idx >= NB * NV) return;
    const float INF = __int_as_float(0x7f800000);
    float mn = INF;
    #pragma unroll
    for (int s = 0; s < SP; s++) mn = fminf(mn, d_pmin[s][idx]);
    float v = sqrtf(fmaxf(mn, 1e-12f));

    float acc = 0.f;
    #pragma unroll
    for (int s = 0; s < SW; s++) acc += d_wnp[s][idx];
    float wn = (2.0f * acc) / 12.566370614359172f;

    out[idx]               = v;
    out[NB * NV + idx]     = (v < 0.02f) ? 1.0f : 0.0f;
    out[2 * NB * NV + idx] = (wn <= 0.99f) ? 1.0f : 0.0f;
}

extern "C" void kernel_launch(void* const* d_in, const int* in_sizes, int n_in,
                              void* d_out, int out_size) {
    const float* verts = (const float*)d_in[0];
    const int*   faces = (const int*)d_in[1];
    const int*   gm    = (const int*)d_in[2];
    float* out = (float*)d_out;

    gather_tris<<<(NB * NF + 255) / 256, 256>>>(verts, faces);

    dim3 gw(54, SW, NB);                 // 1728 blocks, 64 thr
    winding_kernel<<<gw, 64>>>(verts);

    dim3 gp((NV + 511) / 512, SP);       // 336 blocks
    pairwise_kernel<<<gp, 256>>>(verts, gm);

    finalize_kernel<<<(NB * NV + 255) / 256, 256>>>(out);
}